// round 10
// baseline (speedup 1.0000x reference)
#include <cuda_runtime.h>

// Problem constants
#define BB   32
#define TT   400
#define DD   64
#define NBT  (BB*TT)      // 12800 matrices
#define S    72           // shared row stride: 2*S = 144 = 16 mod 32 banks ->
                          // 2-row-paired float4 trailing accesses are phase-conflict-free
#define NB   8            // Cholesky block size

// 0.5 * D * log(2*pi) = 32 * 1.8378770664093453
#define HALF_D_LOG_2PI 58.812066125098784f
#define EPS 1e-6f

__device__ __align__(16) float g_partial[NBT];
__device__ double g_stage[25];
__device__ int    g_count;     // static-zero; reset by last CTA each call

// One CTA (128 threads) per matrix. Blocked right-looking Cholesky, NB=8, on the
// bordered 65x64 system (row 64 = x-mu; corner accumulates -z.z).
//
//  sm[66][S] : rows 0..63 sigma (in place), row 64 = border, row 65 = dummy
//  Pt[2][8][S]: ping-pong TRANSPOSED panel. Panel b is factorized entirely inside
//               Pt[b&1] (contiguous, conflict-free). Pt[(b+1)&1] is filled by the
//               trailing update of block b (transpose folded in for free).
__global__ __launch_bounds__(128)
void chol_ll_kernel(const float* __restrict__ x,
                    const float* __restrict__ mu,
                    const float* __restrict__ sigma)
{
    __shared__ __align__(16) float sm[66 * S];
    __shared__ __align__(16) float Pt[2][NB * S];
    __shared__ float wlog[4];

    const int bt   = blockIdx.x;
    const int tid  = threadIdx.x;
    const int lane = tid & 31;
    const int wid  = tid >> 5;

    // ---- Load sigma (float4, coalesced); fold cols 0..7 transposed into Pt[0] ----
    const float4* src = (const float4*)(sigma + (size_t)bt * (DD * DD));
    #pragma unroll 4
    for (int idx = tid; idx < (DD * DD / 4); idx += 128) {
        float4 v = src[idx];
        int r  = idx >> 4;
        int cb = (idx & 15) << 2;
        *(float4*)&sm[r * S + cb] = v;
        if (cb == 0) {
            Pt[0][0 * S + r] = v.x; Pt[0][1 * S + r] = v.y;
            Pt[0][2 * S + r] = v.z; Pt[0][3 * S + r] = v.w;
        } else if (cb == 4) {
            Pt[0][4 * S + r] = v.x; Pt[0][5 * S + r] = v.y;
            Pt[0][6 * S + r] = v.z; Pt[0][7 * S + r] = v.w;
        }
    }
    // Border row = x - mu; its first 8 entries also seed Pt[0]'s row 64.
    if (tid < DD) {
        float d = x[(size_t)bt * DD + tid] - mu[(size_t)bt * DD + tid];
        sm[64 * S + tid] = d;
        if (tid < NB) Pt[0][tid * S + 64] = d;
    }
    if (tid == 64) sm[64 * S + 64] = 0.f;
    // Zero pads Pt[*][kk][65..67] (border chunk slack; must stay zero)
    if (tid < 48) {
        int buf = tid / 24, r = tid % 24;
        Pt[buf][(r / 3) * S + 65 + (r % 3)] = 0.f;
    }

    float logdet = 0.f;    // partial, in lane0 of warps 0..3 (panel rotates)

    #pragma unroll 1
    for (int b = 0; b < 8; b++) {
        const int b0 = b * NB;
        float* P  = Pt[b & 1];
        float* Pn = Pt[(b + 1) & 1];
        __syncthreads();      // previous trailing (or load) complete

        // ==== Panel: columns b0..b0+7, factorized inside Pt (contiguous). ====
        // Rotate owning warp so panel issue spreads across all 4 SMSPs.
        if (wid == (b & 3)) {
            #pragma unroll
            for (int kk = 0; kk < NB; kk++) {
                const int k = b0 + kk;
                float d    = P[kk * S + k] + EPS;   // EPS folded at pivot read
                float invL = rsqrtf(d);
                if (lane == 0) logdet += 0.5f * __logf(d);

                for (int i = k + 1 + lane; i <= 64; i += 32)
                    P[kk * S + i] *= invL;
                __syncwarp();

                float s[NB];
                #pragma unroll
                for (int jj = kk + 1; jj < NB; jj++) s[jj] = P[kk * S + b0 + jj];
                for (int i = k + 1 + lane; i <= 64; i += 32) {
                    float li = P[kk * S + i];
                    #pragma unroll
                    for (int jj = kk + 1; jj < NB; jj++)
                        P[jj * S + i] = fmaf(-li, s[jj], P[jj * S + i]);
                }
                __syncwarp();
            }
        }
        __syncthreads();      // panel visible to all warps

        // ==== Rank-8 trailing update: rows lo..64, cols lo..row (float4). ====
        // 2 adjacent rows per thread (Pt chunks amortized), p = pow2 column split.
        const int lo = b0 + NB;
        const int c0 = lo >> 2;
        const int m  = 57 - b0;          // trailing rows (odd)
        const int Pr = (m + 1) >> 1;     // row pairs
        int p = 1;
        while ((Pr * (p << 1)) <= 128 && p < 16) p <<= 1;

        if (tid < p * Pr) {
            const int pr = tid / p;
            const int h  = tid % p;
            const int i0 = lo + 2 * pr;
            const int i1 = i0 + 1;
            const bool v1 = (i1 <= 64);

            float Li0[NB], Li1[NB];
            #pragma unroll
            for (int kk = 0; kk < NB; kk++) {
                Li0[kk] = P[kk * S + i0];
                Li1[kk] = v1 ? P[kk * S + i1] : 0.f;
            }
            const int ce0 = i0 >> 2;
            const int ce1 = v1 ? (i1 >> 2) : ce0;
            float* r0 = &sm[i0 * S];
            float* r1 = &sm[i1 * S];     // i1==65 -> dummy row (loads only)

            for (int c = c0 + h; c <= ce1; c += p) {
                float4 a0 = *(float4*)&r0[4 * c];
                float4 a1 = *(float4*)&r1[4 * c];
                #pragma unroll
                for (int kk = 0; kk < NB; kk++) {
                    float4 pk = *(const float4*)&P[kk * S + 4 * c];
                    a0.x = fmaf(-Li0[kk], pk.x, a0.x);
                    a0.y = fmaf(-Li0[kk], pk.y, a0.y);
                    a0.z = fmaf(-Li0[kk], pk.z, a0.z);
                    a0.w = fmaf(-Li0[kk], pk.w, a0.w);
                    a1.x = fmaf(-Li1[kk], pk.x, a1.x);
                    a1.y = fmaf(-Li1[kk], pk.y, a1.y);
                    a1.z = fmaf(-Li1[kk], pk.z, a1.z);
                    a1.w = fmaf(-Li1[kk], pk.w, a1.w);
                }
                if (c <= ce0) *(float4*)&r0[4 * c] = a0;
                if (v1)       *(float4*)&r1[4 * c] = a1;

                // Fold transpose of NEXT panel's columns (lo..lo+7) into Pn.
                if (c == c0) {
                    Pn[0 * S + i0] = a0.x; Pn[1 * S + i0] = a0.y;
                    Pn[2 * S + i0] = a0.z; Pn[3 * S + i0] = a0.w;
                    if (v1) {
                        Pn[0 * S + i1] = a1.x; Pn[1 * S + i1] = a1.y;
                        Pn[2 * S + i1] = a1.z; Pn[3 * S + i1] = a1.w;
                    }
                } else if (c == c0 + 1) {
                    if (c <= ce0) {
                        Pn[4 * S + i0] = a0.x; Pn[5 * S + i0] = a0.y;
                        Pn[6 * S + i0] = a0.z; Pn[7 * S + i0] = a0.w;
                    }
                    if (v1) {
                        Pn[4 * S + i1] = a1.x; Pn[5 * S + i1] = a1.y;
                        Pn[6 * S + i1] = a1.z; Pn[7 * S + i1] = a1.w;
                    }
                }
            }
        }
    }

    __syncthreads();
    if (lane == 0 && wid < 4) wlog[wid] = logdet;
    __syncthreads();
    if (tid == 0) {
        float ld = wlog[0] + wlog[1] + wlog[2] + wlog[3];
        g_partial[bt] = 0.5f * sm[64 * S + 64] - ld - HALF_D_LOG_2PI;
    }
}

// Single-launch deterministic reduction: 25 CTAs x 512 elems; last CTA (by
// atomic ticket) sums the 25 stage values in FIXED order -> deterministic.
__global__ __launch_bounds__(128)
void reduce_ll_kernel(float* __restrict__ out)
{
    __shared__ double red[128];
    const float4 v = ((const float4*)g_partial)[blockIdx.x * 128 + threadIdx.x];
    red[threadIdx.x] = (double)v.x + (double)v.y + (double)v.z + (double)v.w;
    __syncthreads();
    #pragma unroll
    for (int s = 64; s > 0; s >>= 1) {
        if (threadIdx.x < s) red[threadIdx.x] += red[threadIdx.x + s];
        __syncthreads();
    }
    if (threadIdx.x == 0) {
        g_stage[blockIdx.x] = red[0];
        __threadfence();
        int done = atomicAdd(&g_count, 1);
        if (done == 24) {
            __threadfence();
            double t = 0.0;
            #pragma unroll
            for (int i = 0; i < 25; i++) t += g_stage[i];
            out[0] = (float)(-t / (double)BB);
            g_count = 0;   // reset for next graph replay
        }
    }
}

extern "C" void kernel_launch(void* const* d_in, const int* in_sizes, int n_in,
                              void* d_out, int out_size)
{
    // Identify sigma by size; x/mu order is irrelevant (z.z invariant to sign).
    const float* sigma = nullptr;
    const float* v0 = nullptr;
    const float* v1 = nullptr;
    for (int i = 0; i < n_in; i++) {
        if (in_sizes[i] == NBT * DD * DD) {
            sigma = (const float*)d_in[i];
        } else {
            if (!v0) v0 = (const float*)d_in[i];
            else     v1 = (const float*)d_in[i];
        }
    }

    chol_ll_kernel<<<NBT, 128>>>(v0, v1, sigma);
    reduce_ll_kernel<<<25, 128>>>((float*)d_out);
}